// round 4
// baseline (speedup 1.0000x reference)
#include <cuda_runtime.h>
#include <cstdint>

#define NB 12
#define DM 128
#define NH 2
#define HD 64

struct Consts {
    float ta[NH];
    float u[NH];
    float bo;
    float pad;
    // 16B-aligned blocks for float4 loads
    float tb[NH][NB];        // beta' (scaled)
    float gam[NH][NB];       // gamma' (scaled)
    float w[NH][NB];         // vc[k,h] . Wo_h
    float del[NH][NB][NB];   // delta' (scaled); rows of 12 floats = 3 x float4
};

__device__ __align__(16) Consts g_c;
__device__ float g_av[3][DM];          // qa, ka, va
__device__ float g_cv[3][NB][DM];      // qc[b], kc[b], vc[b]
__device__ int g_arrive;

__device__ __forceinline__ float ex2f(float v) {
    float y;
    asm("ex2.approx.f32 %0, %1;" : "=f"(y) : "f"(v));
    return y;
}
__device__ __forceinline__ float warp_sum(float v) {
    v += __shfl_xor_sync(0xffffffffu, v, 16);
    v += __shfl_xor_sync(0xffffffffu, v, 8);
    v += __shfl_xor_sync(0xffffffffu, v, 4);
    v += __shfl_xor_sync(0xffffffffu, v, 2);
    v += __shfl_xor_sync(0xffffffffu, v, 1);
    return v;
}

// ---------------------------------------------------------------------------
// Fused setup: phase 1 = one WARP per length-128 dot product (4992 warps).
// Last block to arrive runs phase 2 (365 length-64 dots, thread-per-dot).
// ---------------------------------------------------------------------------
__global__ __launch_bounds__(256) void spec_setup(
        const float* __restrict__ we, const float* __restrict__ be,
        const float* __restrict__ bp,
        const float* __restrict__ Wq, const float* __restrict__ bq,
        const float* __restrict__ Wk, const float* __restrict__ bk,
        const float* __restrict__ Wv, const float* __restrict__ bv,
        const float* __restrict__ Wo, const float* __restrict__ bo) {
    int gw = (blockIdx.x * blockDim.x + threadIdx.x) >> 5;
    int lane = threadIdx.x & 31;

    // ---- phase 1: project embed vectors through Wq/Wk/Wv ----
    if (gw < 3 * 13 * DM) {
        int m = gw / (13 * DM);
        int r = gw % (13 * DM);
        int v = r / DM;
        int i = r % DM;
        const float* W  = (m == 0) ? Wq : (m == 1) ? Wk : Wv;
        const float* bb = (m == 0) ? bq : (m == 1) ? bk : bv;

        float4 rw = ((const float4*)(W + i * DM))[lane];
        float partial;
        if (v == 0) {
            float4 e = ((const float4*)we)[lane];
            partial = rw.x * e.x + rw.y * e.y + rw.z * e.z + rw.w * e.w;
        } else {
            float4 e = ((const float4*)be)[lane];
            float4 p = ((const float4*)(bp + (v - 1) * DM))[lane];
            partial = rw.x * (e.x + p.x) + rw.y * (e.y + p.y)
                    + rw.z * (e.z + p.z) + rw.w * (e.w + p.w);
        }
        float s = warp_sum(partial);
        if (lane == 0) {
            if (v == 0) g_av[m][i] = s;
            else        g_cv[m][v - 1][i] = s + bb[i];
        }
    }

    // ---- arrival: last block runs phase 2 ----
    __threadfence();
    __syncthreads();
    __shared__ int sLast;
    if (threadIdx.x == 0) {
        int t = atomicAdd(&g_arrive, 1);
        sLast = (t == (int)gridDim.x - 1);
        if (sLast) g_arrive = 0;   // reset for next graph replay
    }
    __syncthreads();
    if (!sLast) return;

    const float cfac = 0.125f * 1.4426950408889634f;  // (1/sqrt(64))*log2(e)
    for (int t = threadIdx.x; t <= NH * 182; t += blockDim.x) {
        if (t == NH * 182) { g_c.bo = bo[0]; continue; }
        int h = t / 182;
        int r = t % 182;
        int off = h * HD;

        const float* a; const float* b; float* dst; float sc = cfac;
        if (r == 0)       { a = &g_av[0][off]; b = &g_av[1][off]; dst = &g_c.ta[h]; }
        else if (r == 1)  { a = &g_av[2][off]; b = Wo + off; dst = &g_c.u[h]; sc = 1.0f; }
        else if (r < 14)  { int bd = r - 2;  a = &g_av[0][off]; b = &g_cv[1][bd][off]; dst = &g_c.tb[h][bd]; }
        else if (r < 26)  { int bd = r - 14; a = &g_cv[0][bd][off]; b = &g_av[1][off]; dst = &g_c.gam[h][bd]; }
        else if (r < 38)  { int bd = r - 26; a = &g_cv[2][bd][off]; b = Wo + off; dst = &g_c.w[h][bd]; sc = 1.0f; }
        else {
            int idx = r - 38, q = idx / NB, k = idx % NB;
            a = &g_cv[0][q][off]; b = &g_cv[1][k][off]; dst = &g_c.del[h][q][k];
        }
        const float4* A = (const float4*)a;
        const float4* B = (const float4*)b;
        float acc = 0.f;
        #pragma unroll
        for (int j = 0; j < HD / 4; j++) {
            float4 av = A[j], bv = B[j];
            acc += av.x * bv.x + av.y * bv.y + av.z * bv.z + av.w * bv.w;
        }
        *dst = acc * sc;
    }
}

// ---------------------------------------------------------------------------
// Main kernel: one thread per token. Scalar core (round-2 proven), but all
// shared-memory constants fetched via float4 (LDS.128) to decongest MIO,
// which MUFU (ex2) shares.
// ---------------------------------------------------------------------------
__global__ __launch_bounds__(128) void spec_main(const float* __restrict__ x,
                                                 float* __restrict__ out, int N) {
    __shared__ __align__(16) Consts sC;
    {
        const float4* src = (const float4*)&g_c;
        float4* dst = (float4*)&sC;
        for (int i = threadIdx.x; i < (int)(sizeof(Consts) / 16); i += blockDim.x)
            dst[i] = src[i];
    }
    __syncthreads();

    int n = blockIdx.x * blockDim.x + threadIdx.x;
    if (n >= N) return;

    const float4* xp = (const float4*)(x + (size_t)n * NB);
    float4 a0 = xp[0], a1 = xp[1], a2 = xp[2];
    float xv[NB] = {a0.x, a0.y, a0.z, a0.w, a1.x, a1.y, a1.z, a1.w,
                    a2.x, a2.y, a2.z, a2.w};

    float delta[NB];
    #pragma unroll
    for (int q = 0; q < NB; q++) delta[q] = sC.bo;

    #pragma unroll
    for (int h = 0; h < NH; h++) {
        float ah = sC.ta[h], uh = sC.u[h];

        // vector loads of per-head constant rows (3x LDS.128 each)
        float tbv[NB], wv[NB], gv[NB];
        #pragma unroll
        for (int j = 0; j < 3; j++) {
            float4 tb4 = ((const float4*)sC.tb[h])[j];
            float4 w4  = ((const float4*)sC.w[h])[j];
            float4 g4  = ((const float4*)sC.gam[h])[j];
            tbv[4*j] = tb4.x; tbv[4*j+1] = tb4.y; tbv[4*j+2] = tb4.z; tbv[4*j+3] = tb4.w;
            wv[4*j]  = w4.x;  wv[4*j+1]  = w4.y;  wv[4*j+2]  = w4.z;  wv[4*j+3]  = w4.w;
            gv[4*j]  = g4.x;  gv[4*j+1]  = g4.y;  gv[4*j+2]  = g4.z;  gv[4*j+3]  = g4.w;
        }

        float t[NB], m[NB];
        #pragma unroll
        for (int k = 0; k < NB; k++) {
            t[k] = fmaf(xv[k], ah, tbv[k]);
            m[k] = fmaf(xv[k], uh, wv[k]);
        }

        #pragma unroll
        for (int q = 0; q < NB; q++) {
            float gq = gv[q];
            float xq = xv[q];
            // del row as 3x LDS.128
            float dl[NB];
            #pragma unroll
            for (int j = 0; j < 3; j++) {
                float4 d4 = ((const float4*)sC.del[h][q])[j];
                dl[4*j] = d4.x; dl[4*j+1] = d4.y; dl[4*j+2] = d4.z; dl[4*j+3] = d4.w;
            }
            float rs = 0.f, ds = 0.f;
            #pragma unroll
            for (int k = 0; k < NB; k++) {
                float s = fmaf(xq, t[k], fmaf(xv[k], gq, dl[k]));
                float e = ex2f(s);
                rs += e;
                ds = fmaf(e, m[k], ds);
            }
            delta[q] += __fdividef(ds, rs);
        }
    }

    float4 o0 = make_float4(xv[0] + delta[0], xv[1] + delta[1], xv[2] + delta[2], xv[3] + delta[3]);
    float4 o1 = make_float4(xv[4] + delta[4], xv[5] + delta[5], xv[6] + delta[6], xv[7] + delta[7]);
    float4 o2 = make_float4(xv[8] + delta[8], xv[9] + delta[9], xv[10] + delta[10], xv[11] + delta[11]);
    float4* op = (float4*)(out + (size_t)n * NB);
    op[0] = o0; op[1] = o1; op[2] = o2;
}

// ---------------------------------------------------------------------------
extern "C" void kernel_launch(void* const* d_in, const int* in_sizes, int n_in,
                              void* d_out, int out_size) {
    const float* x  = (const float*)d_in[0];
    const float* we = (const float*)d_in[1];
    const float* be = (const float*)d_in[2];
    const float* bp = (const float*)d_in[3];
    const float* Wq = (const float*)d_in[4];
    const float* bq = (const float*)d_in[5];
    const float* Wk = (const float*)d_in[6];
    const float* bk = (const float*)d_in[7];
    const float* Wv = (const float*)d_in[8];
    const float* bv = (const float*)d_in[9];
    const float* Wo = (const float*)d_in[10];
    const float* bo = (const float*)d_in[11];
    float* out = (float*)d_out;

    int N = in_sizes[0] / NB;  // 65536 tokens

    // 4992 warps, 8 per block -> 624 blocks (exact)
    spec_setup<<<624, 256>>>(we, be, bp, Wq, bq, Wk, bk, Wv, bv, Wo, bo);
    spec_main<<<(N + 127) / 128, 128>>>(x, out, N);
}

// round 5
// speedup vs baseline: 1.2183x; 1.2183x over previous
#include <cuda_runtime.h>
#include <cstdint>

#define NB 12
#define DM 128
#define NH 2
#define HD 64

struct Consts {
    float ta[NH];
    float u[NH];
    float bo;
    float pad[3];
    float tb[NH][NB];        // beta' (scaled)     16B-aligned rows
    float gam[NH][NB];       // gamma' (scaled)
    float w[NH][NB];         // vc[k,h] . Wo_h
    float del[NH][NB][NB];   // delta' (scaled); rows 48B, 16B-aligned
};

__device__ __align__(16) Consts g_c;
__device__ float g_av[3][DM];          // qa, ka, va
__device__ float g_cv[3][NB][DM];      // qc[b], kc[b], vc[b]

__device__ __forceinline__ float ex2f(float v) {
    float y;
    asm("ex2.approx.f32 %0, %1;" : "=f"(y) : "f"(v));
    return y;
}
__device__ __forceinline__ float warp_sum(float v) {
    v += __shfl_xor_sync(0xffffffffu, v, 16);
    v += __shfl_xor_sync(0xffffffffu, v, 8);
    v += __shfl_xor_sync(0xffffffffu, v, 4);
    v += __shfl_xor_sync(0xffffffffu, v, 2);
    v += __shfl_xor_sync(0xffffffffu, v, 1);
    return v;
}

// ---------------------------------------------------------------------------
// Setup 1: one WARP per length-128 dot product (4992 warps). [round-2 proven]
// ---------------------------------------------------------------------------
__global__ __launch_bounds__(128) void spec_setup1(
        const float* __restrict__ we, const float* __restrict__ be,
        const float* __restrict__ bp,
        const float* __restrict__ Wq, const float* __restrict__ bq,
        const float* __restrict__ Wk, const float* __restrict__ bk,
        const float* __restrict__ Wv, const float* __restrict__ bv) {
    int gw = (blockIdx.x * blockDim.x + threadIdx.x) >> 5;
    int lane = threadIdx.x & 31;
    if (gw >= 3 * 13 * DM) return;
    int m = gw / (13 * DM);
    int r = gw % (13 * DM);
    int v = r / DM;
    int i = r % DM;
    const float* W  = (m == 0) ? Wq : (m == 1) ? Wk : Wv;
    const float* bb = (m == 0) ? bq : (m == 1) ? bk : bv;

    float4 rw = ((const float4*)(W + i * DM))[lane];
    float partial;
    if (v == 0) {
        float4 e = ((const float4*)we)[lane];
        partial = rw.x * e.x + rw.y * e.y + rw.z * e.z + rw.w * e.w;
    } else {
        float4 e = ((const float4*)be)[lane];
        float4 p = ((const float4*)(bp + (v - 1) * DM))[lane];
        partial = rw.x * (e.x + p.x) + rw.y * (e.y + p.y)
                + rw.z * (e.z + p.z) + rw.w * (e.w + p.w);
    }
    float s = warp_sum(partial);
    if (lane == 0) {
        if (v == 0) g_av[m][i] = s;
        else        g_cv[m][v - 1][i] = s + bb[i];
    }
}

// ---------------------------------------------------------------------------
// Setup 2: one WARP per length-64 dot product (365 warps). [round-2 proven]
// ---------------------------------------------------------------------------
__global__ __launch_bounds__(256) void spec_setup2(const float* __restrict__ Wo,
                                                   const float* __restrict__ bo) {
    int gw = (blockIdx.x * blockDim.x + threadIdx.x) >> 5;
    int lane = threadIdx.x & 31;
    const float cfac = 0.125f * 1.4426950408889634f;

    if (gw >= NH * 182) {
        if (gw == NH * 182 && lane == 0) g_c.bo = bo[0];
        return;
    }
    int h = gw / 182;
    int t = gw % 182;
    int off = h * HD;

    const float* a; const float* b; float* dst; float sc = cfac;
    if (t == 0)       { a = &g_av[0][off]; b = &g_av[1][off]; dst = &g_c.ta[h]; }
    else if (t == 1)  { a = &g_av[2][off]; b = Wo + off; dst = &g_c.u[h]; sc = 1.0f; }
    else if (t < 14)  { int bd = t - 2;  a = &g_av[0][off]; b = &g_cv[1][bd][off]; dst = &g_c.tb[h][bd]; }
    else if (t < 26)  { int bd = t - 14; a = &g_cv[0][bd][off]; b = &g_av[1][off]; dst = &g_c.gam[h][bd]; }
    else if (t < 38)  { int bd = t - 26; a = &g_cv[2][bd][off]; b = Wo + off; dst = &g_c.w[h][bd]; sc = 1.0f; }
    else {
        int idx = t - 38, q = idx / NB, k = idx % NB;
        a = &g_cv[0][q][off]; b = &g_cv[1][k][off]; dst = &g_c.del[h][q][k];
    }
    float2 av = ((const float2*)a)[lane];
    float2 bv = ((const float2*)b)[lane];
    float s = warp_sum(av.x * bv.x + av.y * bv.y);
    if (lane == 0) *dst = s * sc;
}

// ---------------------------------------------------------------------------
// Main kernel: TWO threads per token (one per head). 4096 warps -> ~40% occ.
// Each thread does its head's 12x12 attention; head contributions are summed
// with one shfl_xor per q; the even (h=0) thread writes the token.
// del rows consumed directly from float4 components (no scalar array copies).
// ---------------------------------------------------------------------------
__global__ __launch_bounds__(256) void spec_main(const float* __restrict__ x,
                                                 float* __restrict__ out, int N2) {
    __shared__ __align__(16) Consts sC;
    {
        const float4* src = (const float4*)&g_c;
        float4* dst = (float4*)&sC;
        for (int i = threadIdx.x; i < (int)(sizeof(Consts) / 16); i += blockDim.x)
            dst[i] = src[i];
    }
    __syncthreads();

    int t = blockIdx.x * blockDim.x + threadIdx.x;
    if (t >= N2) return;
    int n = t >> 1;
    int h = t & 1;

    const float4* xp = (const float4*)(x + (size_t)n * NB);
    float4 a0 = xp[0], a1 = xp[1], a2 = xp[2];
    float xv[NB] = {a0.x, a0.y, a0.z, a0.w, a1.x, a1.y, a1.z, a1.w,
                    a2.x, a2.y, a2.z, a2.w};

    float ah = sC.ta[h], uh = sC.u[h];

    // t[k] = x_k*alpha + beta_k ; m[k] = x_k*u + w_k  (rows via LDS.128)
    float tk[NB], mk[NB], gv[NB];
    #pragma unroll
    for (int j = 0; j < 3; j++) {
        float4 tb4 = ((const float4*)sC.tb[h])[j];
        float4 w4  = ((const float4*)sC.w[h])[j];
        float4 g4  = ((const float4*)sC.gam[h])[j];
        tk[4*j+0] = fmaf(xv[4*j+0], ah, tb4.x);
        tk[4*j+1] = fmaf(xv[4*j+1], ah, tb4.y);
        tk[4*j+2] = fmaf(xv[4*j+2], ah, tb4.z);
        tk[4*j+3] = fmaf(xv[4*j+3], ah, tb4.w);
        mk[4*j+0] = fmaf(xv[4*j+0], uh, w4.x);
        mk[4*j+1] = fmaf(xv[4*j+1], uh, w4.y);
        mk[4*j+2] = fmaf(xv[4*j+2], uh, w4.z);
        mk[4*j+3] = fmaf(xv[4*j+3], uh, w4.w);
        gv[4*j+0] = g4.x; gv[4*j+1] = g4.y; gv[4*j+2] = g4.z; gv[4*j+3] = g4.w;
    }

    float contrib[NB];
    #pragma unroll
    for (int q = 0; q < NB; q++) {
        float gq = gv[q];
        float xq = xv[q];
        const float4* dr = (const float4*)sC.del[h][q];
        float4 d0 = dr[0], d1 = dr[1], d2 = dr[2];

        float e0  = ex2f(fmaf(xq, tk[0],  fmaf(xv[0],  gq, d0.x)));
        float e1  = ex2f(fmaf(xq, tk[1],  fmaf(xv[1],  gq, d0.y)));
        float e2  = ex2f(fmaf(xq, tk[2],  fmaf(xv[2],  gq, d0.z)));
        float e3  = ex2f(fmaf(xq, tk[3],  fmaf(xv[3],  gq, d0.w)));
        float e4  = ex2f(fmaf(xq, tk[4],  fmaf(xv[4],  gq, d1.x)));
        float e5  = ex2f(fmaf(xq, tk[5],  fmaf(xv[5],  gq, d1.y)));
        float e6  = ex2f(fmaf(xq, tk[6],  fmaf(xv[6],  gq, d1.z)));
        float e7  = ex2f(fmaf(xq, tk[7],  fmaf(xv[7],  gq, d1.w)));
        float e8  = ex2f(fmaf(xq, tk[8],  fmaf(xv[8],  gq, d2.x)));
        float e9  = ex2f(fmaf(xq, tk[9],  fmaf(xv[9],  gq, d2.y)));
        float e10 = ex2f(fmaf(xq, tk[10], fmaf(xv[10], gq, d2.z)));
        float e11 = ex2f(fmaf(xq, tk[11], fmaf(xv[11], gq, d2.w)));

        float rs = ((e0 + e1) + (e2 + e3)) + ((e4 + e5) + (e6 + e7))
                 + ((e8 + e9) + (e10 + e11));
        float ds = fmaf(e0, mk[0], 0.f);
        ds = fmaf(e1,  mk[1],  ds); ds = fmaf(e2,  mk[2],  ds);
        ds = fmaf(e3,  mk[3],  ds); ds = fmaf(e4,  mk[4],  ds);
        ds = fmaf(e5,  mk[5],  ds); ds = fmaf(e6,  mk[6],  ds);
        ds = fmaf(e7,  mk[7],  ds); ds = fmaf(e8,  mk[8],  ds);
        ds = fmaf(e9,  mk[9],  ds); ds = fmaf(e10, mk[10], ds);
        ds = fmaf(e11, mk[11], ds);

        contrib[q] = __fdividef(ds, rs);
    }

    // sum the two heads' contributions across the thread pair
    #pragma unroll
    for (int q = 0; q < NB; q++)
        contrib[q] += __shfl_xor_sync(0xffffffffu, contrib[q], 1);

    if (h == 0) {
        float b = sC.bo;
        float4 o0 = make_float4(xv[0] + contrib[0] + b,  xv[1] + contrib[1] + b,
                                xv[2] + contrib[2] + b,  xv[3] + contrib[3] + b);
        float4 o1 = make_float4(xv[4] + contrib[4] + b,  xv[5] + contrib[5] + b,
                                xv[6] + contrib[6] + b,  xv[7] + contrib[7] + b);
        float4 o2 = make_float4(xv[8] + contrib[8] + b,  xv[9] + contrib[9] + b,
                                xv[10] + contrib[10] + b, xv[11] + contrib[11] + b);
        float4* op = (float4*)(out + (size_t)n * NB);
        op[0] = o0; op[1] = o1; op[2] = o2;
    }
}

// ---------------------------------------------------------------------------
extern "C" void kernel_launch(void* const* d_in, const int* in_sizes, int n_in,
                              void* d_out, int out_size) {
    const float* x  = (const float*)d_in[0];
    const float* we = (const float*)d_in[1];
    const float* be = (const float*)d_in[2];
    const float* bp = (const float*)d_in[3];
    const float* Wq = (const float*)d_in[4];
    const float* bq = (const float*)d_in[5];
    const float* Wk = (const float*)d_in[6];
    const float* bk = (const float*)d_in[7];
    const float* Wv = (const float*)d_in[8];
    const float* bv = (const float*)d_in[9];
    const float* Wo = (const float*)d_in[10];
    const float* bo = (const float*)d_in[11];
    float* out = (float*)d_out;

    int N = in_sizes[0] / NB;   // 65536 tokens
    int N2 = 2 * N;             // thread count for main

    int s1_warps = 3 * 13 * DM;                 // 4992 warps
    spec_setup1<<<(s1_warps + 3) / 4, 128>>>(we, be, bp, Wq, bq, Wk, bk, Wv, bv);

    int s2_warps = NH * 182 + 1;                // 365 warps
    spec_setup2<<<(s2_warps + 7) / 8, 256>>>(Wo, bo);

    spec_main<<<(N2 + 255) / 256, 256>>>(x, out, N2);
}

// round 6
// speedup vs baseline: 1.3864x; 1.1380x over previous
#include <cuda_runtime.h>
#include <cuda_fp16.h>
#include <cstdint>

#define NB 12
#define DM 128
#define NH 2
#define HD 64

struct Consts {
    float ta[NH];
    float u[NH];
    float bo;
    float pad[3];
    float tb[NH][NB];        // beta' (scaled by log2e/sqrt(hd))
    float gam[NH][NB];       // gamma' (scaled)
    float w[NH][NB];         // vc[k,h] . Wo_h
    float del[NH][NB][NB];   // delta' (scaled)
};

__device__ __align__(16) Consts g_c;
__device__ float g_av[3][DM];          // qa, ka, va
__device__ float g_cv[3][NB][DM];      // qc[b], kc[b], vc[b]

__device__ __forceinline__ __half2 h2ex2(__half2 v) {
    uint32_t a = *reinterpret_cast<uint32_t*>(&v), b;
    asm("ex2.approx.f16x2 %0, %1;" : "=r"(b) : "r"(a));
    return *reinterpret_cast<__half2*>(&b);
}
__device__ __forceinline__ float warp_sum(float v) {
    v += __shfl_xor_sync(0xffffffffu, v, 16);
    v += __shfl_xor_sync(0xffffffffu, v, 8);
    v += __shfl_xor_sync(0xffffffffu, v, 4);
    v += __shfl_xor_sync(0xffffffffu, v, 2);
    v += __shfl_xor_sync(0xffffffffu, v, 1);
    return v;
}

// ---------------------------------------------------------------------------
// Setup 1: one WARP per length-128 dot product (4992 warps). [proven]
// ---------------------------------------------------------------------------
__global__ __launch_bounds__(128) void spec_setup1(
        const float* __restrict__ we, const float* __restrict__ be,
        const float* __restrict__ bp,
        const float* __restrict__ Wq, const float* __restrict__ bq,
        const float* __restrict__ Wk, const float* __restrict__ bk,
        const float* __restrict__ Wv, const float* __restrict__ bv) {
    int gw = (blockIdx.x * blockDim.x + threadIdx.x) >> 5;
    int lane = threadIdx.x & 31;
    if (gw >= 3 * 13 * DM) return;
    int m = gw / (13 * DM);
    int r = gw % (13 * DM);
    int v = r / DM;
    int i = r % DM;
    const float* W  = (m == 0) ? Wq : (m == 1) ? Wk : Wv;
    const float* bb = (m == 0) ? bq : (m == 1) ? bk : bv;

    float4 rw = ((const float4*)(W + i * DM))[lane];
    float partial;
    if (v == 0) {
        float4 e = ((const float4*)we)[lane];
        partial = rw.x * e.x + rw.y * e.y + rw.z * e.z + rw.w * e.w;
    } else {
        float4 e = ((const float4*)be)[lane];
        float4 p = ((const float4*)(bp + (v - 1) * DM))[lane];
        partial = rw.x * (e.x + p.x) + rw.y * (e.y + p.y)
                + rw.z * (e.z + p.z) + rw.w * (e.w + p.w);
    }
    float s = warp_sum(partial);
    if (lane == 0) {
        if (v == 0) g_av[m][i] = s;
        else        g_cv[m][v - 1][i] = s + bb[i];
    }
}

// ---------------------------------------------------------------------------
// Setup 2: one WARP per length-64 dot product (365 warps). [proven]
// ---------------------------------------------------------------------------
__global__ __launch_bounds__(256) void spec_setup2(const float* __restrict__ Wo,
                                                   const float* __restrict__ bo) {
    int gw = (blockIdx.x * blockDim.x + threadIdx.x) >> 5;
    int lane = threadIdx.x & 31;
    const float cfac = 0.125f * 1.4426950408889634f;

    if (gw >= NH * 182) {
        if (gw == NH * 182 && lane == 0) g_c.bo = bo[0];
        return;
    }
    int h = gw / 182;
    int t = gw % 182;
    int off = h * HD;

    const float* a; const float* b; float* dst; float sc = cfac;
    if (t == 0)       { a = &g_av[0][off]; b = &g_av[1][off]; dst = &g_c.ta[h]; }
    else if (t == 1)  { a = &g_av[2][off]; b = Wo + off; dst = &g_c.u[h]; sc = 1.0f; }
    else if (t < 14)  { int bd = t - 2;  a = &g_av[0][off]; b = &g_cv[1][bd][off]; dst = &g_c.tb[h][bd]; }
    else if (t < 26)  { int bd = t - 14; a = &g_cv[0][bd][off]; b = &g_av[1][off]; dst = &g_c.gam[h][bd]; }
    else if (t < 38)  { int bd = t - 26; a = &g_cv[2][bd][off]; b = Wo + off; dst = &g_c.w[h][bd]; sc = 1.0f; }
    else {
        int idx = t - 38, q = idx / NB, k = idx % NB;
        a = &g_cv[0][q][off]; b = &g_cv[1][k][off]; dst = &g_c.del[h][q][k];
    }
    float2 av = ((const float2*)a)[lane];
    float2 bv = ((const float2*)b)[lane];
    float s = warp_sum(av.x * bv.x + av.y * bv.y);
    if (lane == 0) *dst = s * sc;
}

// ---------------------------------------------------------------------------
// Main kernel: TWO threads per token (one per head), fp16x2 over k-pairs.
// Logits, exp (ex2.approx.f16x2), and softmax accumulation run packed;
// the divide and head-combine stay in fp32.
// ---------------------------------------------------------------------------
__global__ __launch_bounds__(256) void spec_main(const float* __restrict__ x,
                                                 float* __restrict__ out, int N2) {
    __shared__ __half2 sDel[NH][NB][8];   // 6 used, padded to 8 for alignment
    __shared__ __half2 sTb[NH][6], sW[NH][6];
    __shared__ __half2 sGam[NH][NB];      // broadcast pairs (g,g)
    __shared__ __half2 sTa[NH], sU[NH];
    __shared__ float sBo;

    {
        int td = threadIdx.x;
        // del pairs: NH*NB*6 = 144
        for (int i = td; i < NH * NB * 6; i += blockDim.x) {
            int h = i / (NB * 6);
            int r = i % (NB * 6);
            int q = r / 6, j = r % 6;
            sDel[h][q][j] = __floats2half2_rn(g_c.del[h][q][2 * j],
                                              g_c.del[h][q][2 * j + 1]);
        }
        if (td < NH * 6) {
            int h = td / 6, j = td % 6;
            sTb[h][j] = __floats2half2_rn(g_c.tb[h][2 * j], g_c.tb[h][2 * j + 1]);
            sW[h][j]  = __floats2half2_rn(g_c.w[h][2 * j],  g_c.w[h][2 * j + 1]);
        }
        if (td < NH * NB) {
            int h = td / NB, q = td % NB;
            float g = g_c.gam[h][q];
            sGam[h][q] = __floats2half2_rn(g, g);
        }
        if (td < NH) {
            sTa[td] = __floats2half2_rn(g_c.ta[td], g_c.ta[td]);
            sU[td]  = __floats2half2_rn(g_c.u[td],  g_c.u[td]);
        }
        if (td == 0) sBo = g_c.bo;
    }
    __syncthreads();

    int t = blockIdx.x * blockDim.x + threadIdx.x;
    if (t >= N2) return;
    int n = t >> 1;
    int h = t & 1;

    const float4* xp = (const float4*)(x + (size_t)n * NB);
    float4 a0 = xp[0], a1 = xp[1], a2 = xp[2];
    float xv[NB] = {a0.x, a0.y, a0.z, a0.w, a1.x, a1.y, a1.z, a1.w,
                    a2.x, a2.y, a2.z, a2.w};

    // packed x pairs and per-q broadcasts
    __half2 x2[6];
    #pragma unroll
    for (int j = 0; j < 6; j++) x2[j] = __floats2half2_rn(xv[2 * j], xv[2 * j + 1]);
    __half2 xq2[NB];
    #pragma unroll
    for (int j = 0; j < 6; j++) {
        xq2[2 * j]     = __low2half2(x2[j]);
        xq2[2 * j + 1] = __high2half2(x2[j]);
    }

    __half2 ah2 = sTa[h], uh2 = sU[h];
    __half2 t2[6], m2[6];
    #pragma unroll
    for (int j = 0; j < 6; j++) {
        t2[j] = __hfma2(x2[j], ah2, sTb[h][j]);
        m2[j] = __hfma2(x2[j], uh2, sW[h][j]);
    }

    float contrib[NB];
    #pragma unroll
    for (int q = 0; q < NB; q++) {
        __half2 gq2 = sGam[h][q];
        __half2 xq  = xq2[q];
        __half2 rs2 = __floats2half2_rn(0.f, 0.f);
        __half2 ds2 = rs2;
        #pragma unroll
        for (int j = 0; j < 6; j++) {
            __half2 s2 = __hfma2(xq, t2[j], __hfma2(x2[j], gq2, sDel[h][q][j]));
            __half2 e2 = h2ex2(s2);
            rs2 = __hadd2(rs2, e2);
            ds2 = __hfma2(e2, m2[j], ds2);
        }
        float2 rf = __half22float2(rs2);
        float2 df = __half22float2(ds2);
        contrib[q] = __fdividef(df.x + df.y, rf.x + rf.y);
    }

    // sum the two heads' contributions across the thread pair
    #pragma unroll
    for (int q = 0; q < NB; q++)
        contrib[q] += __shfl_xor_sync(0xffffffffu, contrib[q], 1);

    if (h == 0) {
        float b = sBo;
        float4 o0 = make_float4(xv[0] + contrib[0] + b,  xv[1] + contrib[1] + b,
                                xv[2] + contrib[2] + b,  xv[3] + contrib[3] + b);
        float4 o1 = make_float4(xv[4] + contrib[4] + b,  xv[5] + contrib[5] + b,
                                xv[6] + contrib[6] + b,  xv[7] + contrib[7] + b);
        float4 o2 = make_float4(xv[8] + contrib[8] + b,  xv[9] + contrib[9] + b,
                                xv[10] + contrib[10] + b, xv[11] + contrib[11] + b);
        float4* op = (float4*)(out + (size_t)n * NB);
        op[0] = o0; op[1] = o1; op[2] = o2;
    }
}

// ---------------------------------------------------------------------------
extern "C" void kernel_launch(void* const* d_in, const int* in_sizes, int n_in,
                              void* d_out, int out_size) {
    const float* x  = (const float*)d_in[0];
    const float* we = (const float*)d_in[1];
    const float* be = (const float*)d_in[2];
    const float* bp = (const float*)d_in[3];
    const float* Wq = (const float*)d_in[4];
    const float* bq = (const float*)d_in[5];
    const float* Wk = (const float*)d_in[6];
    const float* bk = (const float*)d_in[7];
    const float* Wv = (const float*)d_in[8];
    const float* bv = (const float*)d_in[9];
    const float* Wo = (const float*)d_in[10];
    const float* bo = (const float*)d_in[11];
    float* out = (float*)d_out;

    int N = in_sizes[0] / NB;   // 65536 tokens
    int N2 = 2 * N;

    int s1_warps = 3 * 13 * DM;                 // 4992 warps
    spec_setup1<<<(s1_warps + 3) / 4, 128>>>(we, be, bp, Wq, bq, Wk, bk, Wv, bv);

    int s2_warps = NH * 182 + 1;                // 365 warps
    spec_setup2<<<(s2_warps + 7) / 8, 256>>>(Wo, bo);

    spec_main<<<(N2 + 255) / 256, 256>>>(x, out, N2);
}